// round 9
// baseline (speedup 1.0000x reference)
#include <cuda_runtime.h>

// Problem constants
#define BB 16
#define MM 4096
#define TT 4
#define DD 256
#define VV 40000
#define CONV 512
#define BD (BB*DD)          // 4096
#define BM (BB*MM)          // 65536
#define ECHUNK 32           // rows per gather block
#define NEB (MM/ECHUNK)     // 128 gather blocks per batch
#define OCHUNK 64           // rows per k_o block
#define NOB (MM/OCHUNK)     // 64 o blocks per batch
#define LBLK 64             // rows per streaming-logit block
#define NLB (MM/LBLK)       // 64 logit blocks per batch
#define PMAXW 128
#define EMB_SZ ((size_t)BB*MM*DD)  // 64MB arrays

// ---------------- device scratch (allocation-free) ----------------
__device__ float g_emb[2*16777216];  // slot0=emb[1], slot1=emb[2]; emb[3] in d_out
__device__ float g_logit[BM];
__device__ float g_uf[BD];
__device__ float g_part[NOB*BD];
__device__ float g_pmax[BB*PMAXW];
__device__ float g_psum[BB*PMAXW];
__device__ float g_smax[BB];
__device__ float g_sinv[BB];
__device__ unsigned int g_cnt[8];    // per-launch completion counters (self-resetting)

// last-block softmax-stat combine: warp w handles batches w, w+8
__device__ __forceinline__ void stats_reduce(int nblk){
    int w = threadIdx.x >> 5, lane = threadIdx.x & 31;
    for(int b = w; b < BB; b += 8){
        float mx = -3.0e38f, sm = 0.f;
        for(int i = lane; i < nblk; i += 32){
            float m = g_pmax[b*PMAXW + i], s = g_psum[b*PMAXW + i];
            float nm = fmaxf(mx, m);
            sm = sm*expf(mx - nm) + s*expf(m - nm);
            mx = nm;
        }
        #pragma unroll
        for(int off = 16; off; off >>= 1){
            float om = __shfl_xor_sync(0xffffffffu, mx, off);
            float os = __shfl_xor_sync(0xffffffffu, sm, off);
            float nm = fmaxf(mx, om);
            sm = sm*expf(mx - nm) + os*expf(om - nm);
            mx = nm;
        }
        if (lane == 0){ g_smax[b] = mx; g_sinv[b] = 1.0f/sm; }
    }
}

// ---------------- mega gather kernel ----------------
// z=0: C3 -> emb3 (d_out);  z=1: C2 -> g_emb slot1;  z=2: C1 -> g_emb slot0 (last, L2-warm)
// z=3: fused hop-0 logits from C0 with uf = query_vector; last z=3 block folds stats.
__global__ void __launch_bounds__(256) k_gather(
        const int* __restrict__ story, const int* __restrict__ kb_len,
        const int* __restrict__ conv_len, const float* __restrict__ hist,
        const float* __restrict__ C, const float* __restrict__ qv,
        const float* __restrict__ gp, float* __restrict__ emb3){
    int z = blockIdx.z, b = blockIdx.y, c = blockIdx.x;
    int m0 = c*ECHUNK;
    int t = threadIdx.x, mg = t >> 6, d4 = t & 63;
    int start = kb_len[b], clen = conv_len[b];
    const float4* hb = reinterpret_cast<const float4*>(hist + (size_t)b*CONV*DD);

    if (z < 3){
        const float4* t4 = reinterpret_cast<const float4*>(C + (size_t)(3 - z)*VV*DD);
        float* dst = (z == 0) ? (emb3 + (size_t)b*MM*DD)
                              : (g_emb + (size_t)(2 - z)*EMB_SZ + (size_t)b*MM*DD);
        #pragma unroll 2
        for(int mi = 0; mi < ECHUNK; mi += 4){
            int m = m0 + mi + mg;
            int4 tok = *reinterpret_cast<const int4*>(story + (size_t)(b*MM + m)*TT);
            float4 a = t4[(size_t)tok.x*64 + d4];
            float4 cc = t4[(size_t)tok.y*64 + d4];
            float4 e = t4[(size_t)tok.z*64 + d4];
            float4 f = t4[(size_t)tok.w*64 + d4];
            float4 acc;
            acc.x = a.x + cc.x + e.x + f.x;
            acc.y = a.y + cc.y + e.y + f.y;
            acc.z = a.z + cc.z + e.z + f.z;
            acc.w = a.w + cc.w + e.w + f.w;
            int r = m - start;
            if (r >= 0 && r < clen){
                float4 hv = hb[(size_t)r*64 + d4];
                acc.x += hv.x; acc.y += hv.y; acc.z += hv.z; acc.w += hv.w;
            }
            reinterpret_cast<float4*>(dst + (size_t)m*DD)[d4] = acc;
        }
    } else {
        // fused emb0 gather + hop-0 logits (emb0 never materialized), uf = qv
        int warp = t >> 5, lane = t & 31;
        __shared__ float4 su[64];
        __shared__ float sw[8][8];
        if (t < 64) su[t] = reinterpret_cast<const float4*>(qv + b*DD)[t];
        __syncthreads();
        float4 u4 = su[d4];
        const float4* t4 = reinterpret_cast<const float4*>(C);
        #pragma unroll
        for(int i = 0; i < 8; ++i){
            int m = m0 + i*4 + mg;
            int4 tok = *reinterpret_cast<const int4*>(story + (size_t)(b*MM + m)*TT);
            float4 a = t4[(size_t)tok.x*64 + d4];
            float4 cc = t4[(size_t)tok.y*64 + d4];
            float4 e = t4[(size_t)tok.z*64 + d4];
            float4 f = t4[(size_t)tok.w*64 + d4];
            float4 acc;
            acc.x = a.x + cc.x + e.x + f.x;
            acc.y = a.y + cc.y + e.y + f.y;
            acc.z = a.z + cc.z + e.z + f.z;
            acc.w = a.w + cc.w + e.w + f.w;
            int r = m - start;
            if (r >= 0 && r < clen){
                float4 hv = hb[(size_t)r*64 + d4];
                acc.x += hv.x; acc.y += hv.y; acc.z += hv.z; acc.w += hv.w;
            }
            float p = acc.x*u4.x + acc.y*u4.y + acc.z*u4.z + acc.w*u4.w;
            #pragma unroll
            for(int off = 16; off; off >>= 1) p += __shfl_down_sync(0xffffffffu, p, off);
            if (lane == 0) sw[warp][i] = p;
        }
        __syncthreads();
        if (t < 32){
            int r = t;   // row r = 4*i + mg
            float v = sw[2*(r&3)][r>>2] + sw[2*(r&3)+1][r>>2];
            v *= gp[b*MM + m0 + r];
            g_logit[b*MM + m0 + r] = v;
            float mx = v;
            #pragma unroll
            for(int off = 16; off; off >>= 1) mx = fmaxf(mx, __shfl_xor_sync(0xffffffffu, mx, off));
            float sm = expf(v - mx);
            #pragma unroll
            for(int off = 16; off; off >>= 1) sm += __shfl_xor_sync(0xffffffffu, sm, off);
            if (r == 0){ g_pmax[b*PMAXW + c] = mx; g_psum[b*PMAXW + c] = sm; }
        }
        // last z==3 block folds the softmax stats
        __threadfence();
        __syncthreads();
        __shared__ unsigned int lastv;
        if (t == 0) lastv = atomicAdd(&g_cnt[0], 1u);
        __syncthreads();
        if (lastv == (unsigned)(NEB*BB - 1)){
            __threadfence();
            stats_reduce(NEB);
            if (t == 0) g_cnt[0] = 0;
        }
    }
}

// streaming logits (hops 1,2) + fused stats in last block
__global__ void __launch_bounds__(256) k_logit(
        int slot, const float* __restrict__ gp, float* __restrict__ out_ext, int cslot){
    int b = blockIdx.y;
    const float* emb = g_emb + (size_t)slot*EMB_SZ;
    __shared__ float4 su[DD/4];
    __shared__ float smax[8], ssum[8];
    if (threadIdx.x < DD/4)
        su[threadIdx.x] = reinterpret_cast<const float4*>(g_uf + b*DD)[threadIdx.x];
    __syncthreads();
    int warp = threadIdx.x >> 5, lane = threadIdx.x & 31;
    int mbase = blockIdx.x*LBLK + warp*8;
    float lv[8];
    #pragma unroll
    for(int i = 0; i < 8; ++i){
        int m = mbase + i;
        const float4* row = reinterpret_cast<const float4*>(emb + ((size_t)b*MM + m)*DD);
        float4 v0 = row[lane], v1 = row[lane + 32];
        float4 u0 = su[lane], u1 = su[lane + 32];
        float acc = v0.x*u0.x + v0.y*u0.y + v0.z*u0.z + v0.w*u0.w
                  + v1.x*u1.x + v1.y*u1.y + v1.z*u1.z + v1.w*u1.w;
        #pragma unroll
        for(int off = 16; off; off >>= 1) acc += __shfl_down_sync(0xffffffffu, acc, off);
        if (lane == 0) acc *= gp[b*MM + m];
        lv[i] = acc;
    }
    if (lane == 0){
        float mx = lv[0];
        #pragma unroll
        for(int i = 1; i < 8; ++i) mx = fmaxf(mx, lv[i]);
        float sm = 0.f;
        #pragma unroll
        for(int i = 0; i < 8; ++i){
            g_logit[b*MM + mbase + i] = lv[i];
            if (out_ext) out_ext[b*MM + mbase + i] = lv[i];
            sm += expf(lv[i] - mx);
        }
        smax[warp] = mx; ssum[warp] = sm;
    }
    __syncthreads();
    if (threadIdx.x == 0){
        float mx = smax[0];
        #pragma unroll
        for(int w = 1; w < 8; ++w) mx = fmaxf(mx, smax[w]);
        float sm = 0.f;
        #pragma unroll
        for(int w = 0; w < 8; ++w) sm += ssum[w]*expf(smax[w] - mx);
        g_pmax[b*PMAXW + blockIdx.x] = mx;
        g_psum[b*PMAXW + blockIdx.x] = sm;
    }
    __threadfence();
    __syncthreads();
    __shared__ unsigned int lastv;
    if (threadIdx.x == 0) lastv = atomicAdd(&g_cnt[cslot], 1u);
    __syncthreads();
    if (lastv == (unsigned)(NLB*BB - 1)){
        __threadfence();
        stats_reduce(NLB);
        if (threadIdx.x == 0) g_cnt[cslot] = 0;
    }
}

// partial o_k with inline softmax; last block folds uf update (+ optional outputs)
__global__ void __launch_bounds__(256) k_o(
        int slot, const float* __restrict__ emb3, const float* __restrict__ gp,
        float* __restrict__ psoft_out, float* __restrict__ out_uf,
        const float* __restrict__ qv, int cslot){
    int b = blockIdx.y, c = blockIdx.x;
    const float* emb = (slot < 2) ? g_emb + (size_t)slot*EMB_SZ : emb3;
    __shared__ float sp[OCHUNK];
    __shared__ float4 sacc[4][64];
    int t = threadIdx.x, rg = t >> 6, d4 = t & 63;
    int m0 = c*OCHUNK;
    if (t < OCHUNK){
        float p = expf(g_logit[b*MM + m0 + t] - g_smax[b]) * g_sinv[b];
        if (psoft_out) psoft_out[b*MM + m0 + t] = p;
        sp[t] = p * gp[b*MM + m0 + t];
    }
    __syncthreads();
    const float4* base = reinterpret_cast<const float4*>(emb + ((size_t)b*MM + m0)*DD);
    float4 acc = make_float4(0.f, 0.f, 0.f, 0.f);
    #pragma unroll 4
    for(int mi = rg; mi < OCHUNK; mi += 4){
        float p = sp[mi];
        float4 v = base[(size_t)mi*64 + d4];
        acc.x += p*v.x; acc.y += p*v.y; acc.z += p*v.z; acc.w += p*v.w;
    }
    sacc[rg][d4] = acc;
    __syncthreads();
    if (t < 64){
        float4 a0 = sacc[0][t], a1 = sacc[1][t], a2 = sacc[2][t], a3 = sacc[3][t];
        float4 r;
        r.x = a0.x + a1.x + a2.x + a3.x;
        r.y = a0.y + a1.y + a2.y + a3.y;
        r.z = a0.z + a1.z + a2.z + a3.z;
        r.w = a0.w + a1.w + a2.w + a3.w;
        reinterpret_cast<float4*>(g_part + (size_t)c*BD + b*DD)[t] = r;
    }
    // last block: uf update (deterministic fixed-order chunk sum)
    __threadfence();
    __syncthreads();
    __shared__ unsigned int lastv;
    if (t == 0) lastv = atomicAdd(&g_cnt[cslot], 1u);
    __syncthreads();
    if (lastv == (unsigned)(NOB*BB - 1)){
        __threadfence();
        for(int i = t; i < BD; i += 256){
            float o = 0.f;
            #pragma unroll 8
            for(int cc = 0; cc < NOB; ++cc) o += g_part[cc*BD + i];
            float basev = qv ? qv[i] : g_uf[i];
            float v = basev + o;
            g_uf[i] = v;
            if (out_uf) out_uf[i] = v;
        }
        if (t == 0) g_cnt[cslot] = 0;
    }
}

// ---------------- launcher (6 kernels total) ----------------
extern "C" void kernel_launch(void* const* d_in, const int* in_sizes, int n_in,
                              void* d_out, int out_size){
    const int*   story = (const int*)  d_in[0];
    const int*   kb    = (const int*)  d_in[1];
    const int*   cl    = (const int*)  d_in[2];
    const float* hist  = (const float*)d_in[4];
    const float* qv    = (const float*)d_in[5];
    const float* gp    = (const float*)d_in[6];
    const float* C     = (const float*)d_in[7];

    float* out        = (float*)d_out;
    float* out_psoft  = out;                 // (B, M)
    float* out_logits = out + BM;            // (B, M)
    float* out_uf     = out + 2*BM;          // (B, D)
    float* out_emb3   = out + 2*BM + BD;     // (B, M, D)

    // Dead layer-loop eliminated; emb[0] fused into hop-0 logits; all gathers
    // in one z-ordered launch; softmax stats + uf updates folded into last blocks.

    k_gather<<<dim3(NEB, BB, 4), 256>>>(story, kb, cl, hist, C, qv, gp, out_emb3);

    // hop 0: o from emb[1] (slot0, L2-warm), uf = qv + o
    k_o<<<dim3(NOB, BB), 256>>>(0, out_emb3, gp, nullptr, nullptr, qv, 1);
    // hop 1
    k_logit<<<dim3(NLB, BB), 256>>>(0, gp, nullptr, 2);
    k_o<<<dim3(NOB, BB), 256>>>(1, out_emb3, gp, nullptr, nullptr, nullptr, 3);
    // hop 2 (writes logits, psoft, uf outputs)
    k_logit<<<dim3(NLB, BB), 256>>>(1, gp, out_logits, 4);
    k_o<<<dim3(NOB, BB), 256>>>(2, out_emb3, gp, out_psoft, out_uf, nullptr, 5);
}

// round 10
// speedup vs baseline: 1.8012x; 1.8012x over previous
#include <cuda_runtime.h>

// Problem constants
#define BB 16
#define MM 4096
#define TT 4
#define DD 256
#define VV 40000
#define CONV 512
#define BD (BB*DD)          // 4096
#define BM (BB*MM)          // 65536
#define ECHUNK 32           // rows per gather block
#define NEB (MM/ECHUNK)     // 128 gather blocks per batch
#define OCHUNK 32           // rows per k_o block (R8-proven)
#define NOB (MM/OCHUNK)     // 128 o blocks per batch
#define LBLK 64             // rows per streaming-logit block
#define NLB (MM/LBLK)       // 64 logit blocks per batch
#define PMAXW 128
#define EMB_SZ ((size_t)BB*MM*DD)  // 64MB arrays

// ---------------- device scratch (allocation-free) ----------------
__device__ float g_emb[2*16777216];  // slot0=emb[1], slot1=emb[2]; emb[3] in d_out
__device__ float g_logit[BM];
__device__ float g_uf[BD];
__device__ float g_part[NOB*BD];
__device__ float g_pmax[BB*PMAXW];
__device__ float g_psum[BB*PMAXW];
__device__ float g_smax[BB];
__device__ float g_sinv[BB];

// ---------------- mega gather kernel (no tails, no fences) ----------------
// z=0: C3 -> emb3 (d_out);  z=1: C2 -> g_emb slot1;  z=2: C1 -> g_emb slot0 (last, L2-warm)
// z=3: fused hop-0 logits from C0 with uf = query_vector (emb0 never materialized)
__global__ void __launch_bounds__(256) k_gather(
        const int* __restrict__ story, const int* __restrict__ kb_len,
        const int* __restrict__ conv_len, const float* __restrict__ hist,
        const float* __restrict__ C, const float* __restrict__ qv,
        const float* __restrict__ gp, float* __restrict__ emb3){
    int z = blockIdx.z, b = blockIdx.y, c = blockIdx.x;
    int m0 = c*ECHUNK;
    int t = threadIdx.x, mg = t >> 6, d4 = t & 63;
    int start = kb_len[b], clen = conv_len[b];
    const float4* hb = reinterpret_cast<const float4*>(hist + (size_t)b*CONV*DD);

    if (z < 3){
        const float4* t4 = reinterpret_cast<const float4*>(C + (size_t)(3 - z)*VV*DD);
        float* dst = (z == 0) ? (emb3 + (size_t)b*MM*DD)
                              : (g_emb + (size_t)(2 - z)*EMB_SZ + (size_t)b*MM*DD);
        #pragma unroll 2
        for(int mi = 0; mi < ECHUNK; mi += 4){
            int m = m0 + mi + mg;
            int4 tok = *reinterpret_cast<const int4*>(story + (size_t)(b*MM + m)*TT);
            float4 a = t4[(size_t)tok.x*64 + d4];
            float4 cc = t4[(size_t)tok.y*64 + d4];
            float4 e = t4[(size_t)tok.z*64 + d4];
            float4 f = t4[(size_t)tok.w*64 + d4];
            float4 acc;
            acc.x = a.x + cc.x + e.x + f.x;
            acc.y = a.y + cc.y + e.y + f.y;
            acc.z = a.z + cc.z + e.z + f.z;
            acc.w = a.w + cc.w + e.w + f.w;
            int r = m - start;
            if (r >= 0 && r < clen){
                float4 hv = hb[(size_t)r*64 + d4];
                acc.x += hv.x; acc.y += hv.y; acc.z += hv.z; acc.w += hv.w;
            }
            reinterpret_cast<float4*>(dst + (size_t)m*DD)[d4] = acc;
        }
    } else {
        int warp = t >> 5, lane = t & 31;
        __shared__ float4 su[64];
        __shared__ float sw[8][8];
        if (t < 64) su[t] = reinterpret_cast<const float4*>(qv + b*DD)[t];
        __syncthreads();
        float4 u4 = su[d4];
        const float4* t4 = reinterpret_cast<const float4*>(C);
        #pragma unroll
        for(int i = 0; i < 8; ++i){
            int m = m0 + i*4 + mg;
            int4 tok = *reinterpret_cast<const int4*>(story + (size_t)(b*MM + m)*TT);
            float4 a = t4[(size_t)tok.x*64 + d4];
            float4 cc = t4[(size_t)tok.y*64 + d4];
            float4 e = t4[(size_t)tok.z*64 + d4];
            float4 f = t4[(size_t)tok.w*64 + d4];
            float4 acc;
            acc.x = a.x + cc.x + e.x + f.x;
            acc.y = a.y + cc.y + e.y + f.y;
            acc.z = a.z + cc.z + e.z + f.z;
            acc.w = a.w + cc.w + e.w + f.w;
            int r = m - start;
            if (r >= 0 && r < clen){
                float4 hv = hb[(size_t)r*64 + d4];
                acc.x += hv.x; acc.y += hv.y; acc.z += hv.z; acc.w += hv.w;
            }
            float p = acc.x*u4.x + acc.y*u4.y + acc.z*u4.z + acc.w*u4.w;
            #pragma unroll
            for(int off = 16; off; off >>= 1) p += __shfl_down_sync(0xffffffffu, p, off);
            if (lane == 0) sw[warp][i] = p;
        }
        __syncthreads();
        if (t < 32){
            int r = t;   // row r = 4*i + mg
            float v = sw[2*(r&3)][r>>2] + sw[2*(r&3)+1][r>>2];
            v *= gp[b*MM + m0 + r];
            g_logit[b*MM + m0 + r] = v;
            float mx = v;
            #pragma unroll
            for(int off = 16; off; off >>= 1) mx = fmaxf(mx, __shfl_xor_sync(0xffffffffu, mx, off));
            float sm = expf(v - mx);
            #pragma unroll
            for(int off = 16; off; off >>= 1) sm += __shfl_xor_sync(0xffffffffu, sm, off);
            if (r == 0){ g_pmax[b*PMAXW + c] = mx; g_psum[b*PMAXW + c] = sm; }
        }
    }
}

// streaming logits (hops 1,2)   [R8-proven]
__global__ void __launch_bounds__(256) k_logit(
        int slot, const float* __restrict__ gp, float* __restrict__ out_ext){
    int b = blockIdx.y;
    const float* emb = g_emb + (size_t)slot*EMB_SZ;
    __shared__ float4 su[DD/4];
    __shared__ float smax[8], ssum[8];
    if (threadIdx.x < DD/4)
        su[threadIdx.x] = reinterpret_cast<const float4*>(g_uf + b*DD)[threadIdx.x];
    __syncthreads();
    int warp = threadIdx.x >> 5, lane = threadIdx.x & 31;
    int mbase = blockIdx.x*LBLK + warp*8;
    float lv[8];
    #pragma unroll
    for(int i = 0; i < 8; ++i){
        int m = mbase + i;
        const float4* row = reinterpret_cast<const float4*>(emb + ((size_t)b*MM + m)*DD);
        float4 v0 = row[lane], v1 = row[lane + 32];
        float4 u0 = su[lane], u1 = su[lane + 32];
        float acc = v0.x*u0.x + v0.y*u0.y + v0.z*u0.z + v0.w*u0.w
                  + v1.x*u1.x + v1.y*u1.y + v1.z*u1.z + v1.w*u1.w;
        #pragma unroll
        for(int off = 16; off; off >>= 1) acc += __shfl_down_sync(0xffffffffu, acc, off);
        if (lane == 0) acc *= gp[b*MM + m];
        lv[i] = acc;
    }
    if (lane == 0){
        float mx = lv[0];
        #pragma unroll
        for(int i = 1; i < 8; ++i) mx = fmaxf(mx, lv[i]);
        float sm = 0.f;
        #pragma unroll
        for(int i = 0; i < 8; ++i){
            g_logit[b*MM + mbase + i] = lv[i];
            if (out_ext) out_ext[b*MM + mbase + i] = lv[i];
            sm += expf(lv[i] - mx);
        }
        smax[warp] = mx; ssum[warp] = sm;
    }
    __syncthreads();
    if (threadIdx.x == 0){
        float mx = smax[0];
        #pragma unroll
        for(int w = 1; w < 8; ++w) mx = fmaxf(mx, smax[w]);
        float sm = 0.f;
        #pragma unroll
        for(int w = 0; w < 8; ++w) sm += ssum[w]*expf(smax[w] - mx);
        g_pmax[b*PMAXW + blockIdx.x] = mx;
        g_psum[b*PMAXW + blockIdx.x] = sm;
    }
}

// combine nblk per-block softmax partials per batch: warp w = batch b   [R8-proven]
__global__ void __launch_bounds__(512) k_stats(int nblk){
    int w = threadIdx.x >> 5, lane = threadIdx.x & 31;
    float mx = -3.0e38f, sm = 0.f;
    for(int i = lane; i < nblk; i += 32){
        float m = g_pmax[w*PMAXW + i], s = g_psum[w*PMAXW + i];
        float nm = fmaxf(mx, m);
        sm = sm*expf(mx - nm) + s*expf(m - nm);
        mx = nm;
    }
    #pragma unroll
    for(int off = 16; off; off >>= 1){
        float om = __shfl_xor_sync(0xffffffffu, mx, off);
        float os = __shfl_xor_sync(0xffffffffu, sm, off);
        float nm = fmaxf(mx, om);
        sm = sm*expf(mx - nm) + os*expf(om - nm);
        mx = nm;
    }
    if (lane == 0){ g_smax[w] = mx; g_sinv[w] = 1.0f/sm; }
}

// partial o_k with inline softmax   [R8-proven]
__global__ void __launch_bounds__(256) k_o(
        int slot, const float* __restrict__ emb3, const float* __restrict__ gp,
        float* __restrict__ psoft_out){
    int b = blockIdx.y, c = blockIdx.x;
    const float* emb = (slot < 2) ? g_emb + (size_t)slot*EMB_SZ : emb3;
    __shared__ float sp[OCHUNK];
    __shared__ float4 sacc[4][64];
    int t = threadIdx.x, rg = t >> 6, d4 = t & 63;
    int m0 = c*OCHUNK;
    if (t < OCHUNK){
        float p = expf(g_logit[b*MM + m0 + t] - g_smax[b]) * g_sinv[b];
        if (psoft_out) psoft_out[b*MM + m0 + t] = p;
        sp[t] = p * gp[b*MM + m0 + t];
    }
    __syncthreads();
    const float4* base = reinterpret_cast<const float4*>(emb + ((size_t)b*MM + m0)*DD);
    float4 acc = make_float4(0.f, 0.f, 0.f, 0.f);
    #pragma unroll
    for(int mi = rg; mi < OCHUNK; mi += 4){
        float p = sp[mi];
        float4 v = base[(size_t)mi*64 + d4];
        acc.x += p*v.x; acc.y += p*v.y; acc.z += p*v.z; acc.w += p*v.w;
    }
    sacc[rg][d4] = acc;
    __syncthreads();
    if (t < 64){
        float4 a0 = sacc[0][t], a1 = sacc[1][t], a2 = sacc[2][t], a3 = sacc[3][t];
        float4 r;
        r.x = a0.x + a1.x + a2.x + a3.x;
        r.y = a0.y + a1.y + a2.y + a3.y;
        r.z = a0.z + a1.z + a2.z + a3.z;
        r.w = a0.w + a1.w + a2.w + a3.w;
        reinterpret_cast<float4*>(g_part + (size_t)c*BD + b*DD)[t] = r;
    }
}

// uf = base + reduced partials; optionally write to d_out. base = qv (hop0) or g_uf.
__global__ void k_uf_add(const float* __restrict__ base_qv, float* __restrict__ out){
    int b = blockIdx.x, d = threadIdx.x;
    float o = 0.f;
    #pragma unroll
    for(int c = 0; c < NOB; ++c) o += g_part[c*BD + b*DD + d];
    float basev = base_qv ? base_qv[b*DD + d] : g_uf[b*DD + d];
    float v = basev + o;
    g_uf[b*DD + d] = v;
    if (out) out[b*DD + d] = v;
}

// ---------------- launcher ----------------
extern "C" void kernel_launch(void* const* d_in, const int* in_sizes, int n_in,
                              void* d_out, int out_size){
    const int*   story = (const int*)  d_in[0];
    const int*   kb    = (const int*)  d_in[1];
    const int*   cl    = (const int*)  d_in[2];
    const float* hist  = (const float*)d_in[4];
    const float* qv    = (const float*)d_in[5];
    const float* gp    = (const float*)d_in[6];
    const float* C     = (const float*)d_in[7];

    float* out        = (float*)d_out;
    float* out_psoft  = out;                 // (B, M)
    float* out_logits = out + BM;            // (B, M)
    float* out_uf     = out + 2*BM;          // (B, D)
    float* out_emb3   = out + 2*BM + BD;     // (B, M, D)

    // Dead layer-loop eliminated; emb[0] fused into hop-0 logits (z=3 of the
    // single z-ordered gather launch). No cross-block sync anywhere.

    k_gather<<<dim3(NEB, BB, 4), 256>>>(story, kb, cl, hist, C, qv, gp, out_emb3);

    // hop 0: o from emb[1] (slot0, L2-warm); uf = qv + o
    k_stats<<<1, 512>>>(NEB);
    k_o<<<dim3(NOB, BB), 256>>>(0, out_emb3, gp, nullptr);
    k_uf_add<<<BB, DD>>>(qv, nullptr);

    // hop 1
    k_logit<<<dim3(NLB, BB), 256>>>(0, gp, nullptr);
    k_stats<<<1, 512>>>(NLB);
    k_o<<<dim3(NOB, BB), 256>>>(1, out_emb3, gp, nullptr);
    k_uf_add<<<BB, DD>>>(nullptr, nullptr);

    // hop 2 (writes logits, psoft, uf outputs)
    k_logit<<<dim3(NLB, BB), 256>>>(1, gp, out_logits);
    k_stats<<<1, 512>>>(NLB);
    k_o<<<dim3(NOB, BB), 256>>>(2, out_emb3, gp, out_psoft);
    k_uf_add<<<BB, DD>>>(nullptr, out_uf);
}

// round 11
// speedup vs baseline: 1.8536x; 1.0291x over previous
#include <cuda_runtime.h>

// Problem constants
#define BB 16
#define MM 4096
#define TT 4
#define DD 256
#define VV 40000
#define CONV 512
#define BD (BB*DD)          // 4096
#define BM (BB*MM)          // 65536
#define ECHUNK 32           // rows per gather block
#define NEB (MM/ECHUNK)     // 128 gather blocks per batch
#define OCHUNK 32           // rows per k_o block
#define NOB (MM/OCHUNK)     // 128 o blocks per batch
#define LBLK 64             // rows per streaming-logit block
#define NLB (MM/LBLK)       // 64 logit blocks per batch
#define PMAXW 128
#define EMB_SZ ((size_t)BB*MM*DD)  // 64MB arrays

// ---------------- device scratch (allocation-free) ----------------
__device__ float g_emb[2*16777216];  // slot0=emb[1], slot1=emb[2]; emb[3] in d_out
__device__ float g_logit[BM];
__device__ float g_uf[BD];
__device__ float g_part[NOB*BD];
__device__ float g_pmax[BB*PMAXW];
__device__ float g_psum[BB*PMAXW];

// ---------------- mega gather kernel ----------------
// z=0: C3 -> emb3 (d_out);  z=1: C2 -> g_emb slot1;  z=2: C1 -> g_emb slot0 (last, L2-warm)
// z=3: fused hop-0 logits from C0 with uf = query_vector (emb0 never materialized)
__global__ void __launch_bounds__(256) k_gather(
        const int* __restrict__ story, const int* __restrict__ kb_len,
        const int* __restrict__ conv_len, const float* __restrict__ hist,
        const float* __restrict__ C, const float* __restrict__ qv,
        const float* __restrict__ gp, float* __restrict__ emb3){
    int z = blockIdx.z, b = blockIdx.y, c = blockIdx.x;
    int m0 = c*ECHUNK;
    int t = threadIdx.x, mg = t >> 6, d4 = t & 63;
    int start = kb_len[b], clen = conv_len[b];
    const float4* hb = reinterpret_cast<const float4*>(hist + (size_t)b*CONV*DD);

    if (z < 3){
        const float4* t4 = reinterpret_cast<const float4*>(C + (size_t)(3 - z)*VV*DD);
        float* dst = (z == 0) ? (emb3 + (size_t)b*MM*DD)
                              : (g_emb + (size_t)(2 - z)*EMB_SZ + (size_t)b*MM*DD);
        #pragma unroll 2
        for(int mi = 0; mi < ECHUNK; mi += 4){
            int m = m0 + mi + mg;
            int4 tok = *reinterpret_cast<const int4*>(story + (size_t)(b*MM + m)*TT);
            float4 a = t4[(size_t)tok.x*64 + d4];
            float4 cc = t4[(size_t)tok.y*64 + d4];
            float4 e = t4[(size_t)tok.z*64 + d4];
            float4 f = t4[(size_t)tok.w*64 + d4];
            float4 acc;
            acc.x = a.x + cc.x + e.x + f.x;
            acc.y = a.y + cc.y + e.y + f.y;
            acc.z = a.z + cc.z + e.z + f.z;
            acc.w = a.w + cc.w + e.w + f.w;
            int r = m - start;
            if (r >= 0 && r < clen){
                float4 hv = hb[(size_t)r*64 + d4];
                acc.x += hv.x; acc.y += hv.y; acc.z += hv.z; acc.w += hv.w;
            }
            reinterpret_cast<float4*>(dst + (size_t)m*DD)[d4] = acc;
        }
    } else {
        int warp = t >> 5, lane = t & 31;
        __shared__ float4 su[64];
        __shared__ float sw[8][8];
        if (t < 64) su[t] = reinterpret_cast<const float4*>(qv + b*DD)[t];
        __syncthreads();
        float4 u4 = su[d4];
        const float4* t4 = reinterpret_cast<const float4*>(C);
        #pragma unroll
        for(int i = 0; i < 8; ++i){
            int m = m0 + i*4 + mg;
            int4 tok = *reinterpret_cast<const int4*>(story + (size_t)(b*MM + m)*TT);
            float4 a = t4[(size_t)tok.x*64 + d4];
            float4 cc = t4[(size_t)tok.y*64 + d4];
            float4 e = t4[(size_t)tok.z*64 + d4];
            float4 f = t4[(size_t)tok.w*64 + d4];
            float4 acc;
            acc.x = a.x + cc.x + e.x + f.x;
            acc.y = a.y + cc.y + e.y + f.y;
            acc.z = a.z + cc.z + e.z + f.z;
            acc.w = a.w + cc.w + e.w + f.w;
            int r = m - start;
            if (r >= 0 && r < clen){
                float4 hv = hb[(size_t)r*64 + d4];
                acc.x += hv.x; acc.y += hv.y; acc.z += hv.z; acc.w += hv.w;
            }
            float p = acc.x*u4.x + acc.y*u4.y + acc.z*u4.z + acc.w*u4.w;
            #pragma unroll
            for(int off = 16; off; off >>= 1) p += __shfl_down_sync(0xffffffffu, p, off);
            if (lane == 0) sw[warp][i] = p;
        }
        __syncthreads();
        if (t < 32){
            int r = t;   // row r = 4*i + mg
            float v = sw[2*(r&3)][r>>2] + sw[2*(r&3)+1][r>>2];
            v *= gp[b*MM + m0 + r];
            g_logit[b*MM + m0 + r] = v;
            float mx = v;
            #pragma unroll
            for(int off = 16; off; off >>= 1) mx = fmaxf(mx, __shfl_xor_sync(0xffffffffu, mx, off));
            float sm = expf(v - mx);
            #pragma unroll
            for(int off = 16; off; off >>= 1) sm += __shfl_xor_sync(0xffffffffu, sm, off);
            if (r == 0){ g_pmax[b*PMAXW + c] = mx; g_psum[b*PMAXW + c] = sm; }
        }
    }
}

// streaming logits (hops 1,2)   [proven]
__global__ void __launch_bounds__(256) k_logit(
        int slot, const float* __restrict__ gp, float* __restrict__ out_ext){
    int b = blockIdx.y;
    const float* emb = g_emb + (size_t)slot*EMB_SZ;
    __shared__ float4 su[DD/4];
    __shared__ float smax[8], ssum[8];
    if (threadIdx.x < DD/4)
        su[threadIdx.x] = reinterpret_cast<const float4*>(g_uf + b*DD)[threadIdx.x];
    __syncthreads();
    int warp = threadIdx.x >> 5, lane = threadIdx.x & 31;
    int mbase = blockIdx.x*LBLK + warp*8;
    float lv[8];
    #pragma unroll
    for(int i = 0; i < 8; ++i){
        int m = mbase + i;
        const float4* row = reinterpret_cast<const float4*>(emb + ((size_t)b*MM + m)*DD);
        float4 v0 = row[lane], v1 = row[lane + 32];
        float4 u0 = su[lane], u1 = su[lane + 32];
        float acc = v0.x*u0.x + v0.y*u0.y + v0.z*u0.z + v0.w*u0.w
                  + v1.x*u1.x + v1.y*u1.y + v1.z*u1.z + v1.w*u1.w;
        #pragma unroll
        for(int off = 16; off; off >>= 1) acc += __shfl_down_sync(0xffffffffu, acc, off);
        if (lane == 0) acc *= gp[b*MM + m];
        lv[i] = acc;
    }
    if (lane == 0){
        float mx = lv[0];
        #pragma unroll
        for(int i = 1; i < 8; ++i) mx = fmaxf(mx, lv[i]);
        float sm = 0.f;
        #pragma unroll
        for(int i = 0; i < 8; ++i){
            g_logit[b*MM + mbase + i] = lv[i];
            if (out_ext) out_ext[b*MM + mbase + i] = lv[i];
            sm += expf(lv[i] - mx);
        }
        smax[warp] = mx; ssum[warp] = sm;
    }
    __syncthreads();
    if (threadIdx.x == 0){
        float mx = smax[0];
        #pragma unroll
        for(int w = 1; w < 8; ++w) mx = fmaxf(mx, smax[w]);
        float sm = 0.f;
        #pragma unroll
        for(int w = 0; w < 8; ++w) sm += ssum[w]*expf(smax[w] - mx);
        g_pmax[b*PMAXW + blockIdx.x] = mx;
        g_psum[b*PMAXW + blockIdx.x] = sm;
    }
}

// partial o_k; warp-0 prologue recomputes softmax stats for batch b from g_pmax/g_psum
// (fixed reduction order -> bitwise-identical in every block; no cross-block sync).
__global__ void __launch_bounds__(256) k_o(
        int slot, int nblk, const float* __restrict__ emb3, const float* __restrict__ gp,
        float* __restrict__ psoft_out){
    int b = blockIdx.y, c = blockIdx.x;
    const float* emb = (slot < 2) ? g_emb + (size_t)slot*EMB_SZ : emb3;
    __shared__ float sp[OCHUNK];
    __shared__ float4 sacc[4][64];
    __shared__ float s_stat[2];
    int t = threadIdx.x, rg = t >> 6, d4 = t & 63;
    int lane = t & 31;
    int m0 = c*OCHUNK;
    if (t < 32){
        float mx = -3.0e38f, sm = 0.f;
        for(int i = lane; i < nblk; i += 32){
            float m = g_pmax[b*PMAXW + i], s = g_psum[b*PMAXW + i];
            float nm = fmaxf(mx, m);
            sm = sm*expf(mx - nm) + s*expf(m - nm);
            mx = nm;
        }
        #pragma unroll
        for(int off = 16; off; off >>= 1){
            float om = __shfl_xor_sync(0xffffffffu, mx, off);
            float os = __shfl_xor_sync(0xffffffffu, sm, off);
            float nm = fmaxf(mx, om);
            sm = sm*expf(mx - nm) + os*expf(om - nm);
            mx = nm;
        }
        if (lane == 0){ s_stat[0] = mx; s_stat[1] = 1.0f/sm; }
    }
    __syncthreads();
    if (t < OCHUNK){
        float p = expf(g_logit[b*MM + m0 + t] - s_stat[0]) * s_stat[1];
        if (psoft_out) psoft_out[b*MM + m0 + t] = p;
        sp[t] = p * gp[b*MM + m0 + t];
    }
    __syncthreads();
    const float4* base = reinterpret_cast<const float4*>(emb + ((size_t)b*MM + m0)*DD);
    float4 acc = make_float4(0.f, 0.f, 0.f, 0.f);
    #pragma unroll
    for(int mi = rg; mi < OCHUNK; mi += 4){
        float p = sp[mi];
        float4 v = base[(size_t)mi*64 + d4];
        acc.x += p*v.x; acc.y += p*v.y; acc.z += p*v.z; acc.w += p*v.w;
    }
    sacc[rg][d4] = acc;
    __syncthreads();
    if (t < 64){
        float4 a0 = sacc[0][t], a1 = sacc[1][t], a2 = sacc[2][t], a3 = sacc[3][t];
        float4 r;
        r.x = a0.x + a1.x + a2.x + a3.x;
        r.y = a0.y + a1.y + a2.y + a3.y;
        r.z = a0.z + a1.z + a2.z + a3.z;
        r.w = a0.w + a1.w + a2.w + a3.w;
        reinterpret_cast<float4*>(g_part + (size_t)c*BD + b*DD)[t] = r;
    }
}

// uf = base + reduced partials (4-way parallel chunks + smem combine; deterministic)
__global__ void __launch_bounds__(1024) k_uf_add(const float* __restrict__ base_qv,
                                                 float* __restrict__ out){
    int b = blockIdx.x;
    int q = threadIdx.x >> 8, d = threadIdx.x & 255;
    __shared__ float s[4][256];
    float o = 0.f;
    #pragma unroll 8
    for(int c = q; c < NOB; c += 4) o += g_part[c*BD + b*DD + d];
    s[q][d] = o;
    __syncthreads();
    if (q == 0){
        float basev = base_qv ? base_qv[b*DD + d] : g_uf[b*DD + d];
        float v = basev + ((s[0][d] + s[1][d]) + (s[2][d] + s[3][d]));
        g_uf[b*DD + d] = v;
        if (out) out[b*DD + d] = v;
    }
}

// ---------------- launcher (10 kernels total) ----------------
extern "C" void kernel_launch(void* const* d_in, const int* in_sizes, int n_in,
                              void* d_out, int out_size){
    const int*   story = (const int*)  d_in[0];
    const int*   kb    = (const int*)  d_in[1];
    const int*   cl    = (const int*)  d_in[2];
    const float* hist  = (const float*)d_in[4];
    const float* qv    = (const float*)d_in[5];
    const float* gp    = (const float*)d_in[6];
    const float* C     = (const float*)d_in[7];

    float* out        = (float*)d_out;
    float* out_psoft  = out;                 // (B, M)
    float* out_logits = out + BM;            // (B, M)
    float* out_uf     = out + 2*BM;          // (B, D)
    float* out_emb3   = out + 2*BM + BD;     // (B, M, D)

    // Dead layer-loop eliminated; emb[0] fused into hop-0 logits (z=3 of the
    // single z-ordered gather launch). Softmax stats recomputed per-k_o-block
    // (deterministic, no cross-block sync). No fences anywhere.

    k_gather<<<dim3(NEB, BB, 4), 256>>>(story, kb, cl, hist, C, qv, gp, out_emb3);

    // hop 0: o from emb[1] (slot0, L2-warm); uf = qv + o
    k_o<<<dim3(NOB, BB), 256>>>(0, NEB, out_emb3, gp, nullptr);
    k_uf_add<<<BB, 1024>>>(qv, nullptr);

    // hop 1
    k_logit<<<dim3(NLB, BB), 256>>>(0, gp, nullptr);
    k_o<<<dim3(NOB, BB), 256>>>(1, NLB, out_emb3, gp, nullptr);
    k_uf_add<<<BB, 1024>>>(nullptr, nullptr);

    // hop 2 (writes logits, psoft, uf outputs)
    k_logit<<<dim3(NLB, BB), 256>>>(1, gp, out_logits);
    k_o<<<dim3(NOB, BB), 256>>>(2, NLB, out_emb3, gp, out_psoft);
    k_uf_add<<<BB, 1024>>>(nullptr, out_uf);
}